// round 2
// baseline (speedup 1.0000x reference)
#include <cuda_runtime.h>
#include <math.h>

#define B_  4
#define C_  64
#define HH  128
#define WW  128
#define F_  5
#define L_  512
#define NH_ 128

typedef unsigned long long u64;

__device__ __forceinline__ u64 ffma2(u64 a, u64 b, u64 c) {
    u64 d;
    asm("fma.rn.f32x2 %0, %1, %2, %3;" : "=l"(d) : "l"(a), "l"(b), "l"(c));
    return d;
}

// ---------------- device scratch ----------------
__device__ float g_mu[B_*F_*L_];                 // relu(fc(codes))         [b,f,l]
__device__ unsigned char g_rmap[B_*HH*WW];       // region index per pixel (5 = none)
__device__ float g_Tg[B_*9*F_*C_];               // [b][tap][f][c]
__device__ float g_Tb[B_*9*F_*C_];
__device__ float g_actv[(size_t)B_*NH_*HH*WW];   // SPADE shared activation (33.5MB)
__device__ float g_mean[B_*C_];
__device__ float g_rsig[B_*C_];

// ---------------- mu = relu(codes @ fc_w^T + fc_b) ----------------
__global__ void mu_kernel(const float* __restrict__ codes,
                          const float* __restrict__ fc_w,
                          const float* __restrict__ fc_b) {
    __shared__ float sc[L_];
    int bf = blockIdx.x;
    int f = bf % F_;
    int k = threadIdx.x;
    sc[k] = codes[bf*L_ + k];
    __syncthreads();
    const float* wp = fc_w + ((size_t)f*L_ + k)*L_;
    float acc = fc_b[f*L_ + k];
    #pragma unroll 4
    for (int l = 0; l < L_; ++l) acc = fmaf(sc[l], wp[l], acc);
    g_mu[bf*L_ + k] = fmaxf(acc, 0.f);
}

// ---------------- region map: last j with segmap>0, else 5 ----------------
__global__ void region_kernel(const float* __restrict__ seg) {
    int p = blockIdx.x*256 + threadIdx.x;
    if (p >= B_*HH*WW) return;
    int b = p >> 14, pix = p & 16383;
    int r = 5;
    #pragma unroll
    for (int j = 0; j < F_; ++j)
        if (seg[(b*F_ + j)*16384 + pix] > 0.f) r = j;
    g_rmap[p] = (unsigned char)r;
}

// ---------------- tables T[b,tap,f,c] = sum_l convW[c,l,tap]*mu[b,f,l] ----------------
__global__ void table_kernel(const float* __restrict__ cgw,
                             const float* __restrict__ cbw) {
    int gt = blockIdx.x*256 + threadIdx.x;
    int e = gt >> 5, lane = gt & 31;
    int tbl = e / 11520; int r = e - tbl*11520;
    int b = r / 2880;    int r2 = r - b*2880;
    int tap = r2 / 320;  int r3 = r2 - tap*320;
    int f = r3 >> 6;     int c = r3 & 63;
    int dy = tap / 3, dx = tap - dy*3;
    const float* w = tbl ? cbw : cgw;
    const float* m = g_mu + (b*F_ + f)*L_;
    float s = 0.f;
    for (int l = lane; l < L_; l += 32)
        s = fmaf(w[(((size_t)c*L_ + l)*3 + dy)*3 + dx], m[l], s);
    #pragma unroll
    for (int o = 16; o > 0; o >>= 1) s += __shfl_down_sync(0xffffffffu, s, o);
    if (lane == 0)
        (tbl ? g_Tb : g_Tg)[((b*9 + tap)*F_ + f)*64 + c] = s;
}

// ---------------- instance norm stats ----------------
__global__ void stats_kernel(const float* __restrict__ x) {
    int bc = blockIdx.x;
    const float* p = x + (size_t)bc*16384;
    float s = 0.f, s2 = 0.f;
    for (int i = threadIdx.x; i < 16384; i += 256) {
        float v = p[i]; s += v; s2 = fmaf(v, v, s2);
    }
    __shared__ float sh1[256], sh2[256];
    sh1[threadIdx.x] = s; sh2[threadIdx.x] = s2;
    __syncthreads();
    for (int o = 128; o > 0; o >>= 1) {
        if (threadIdx.x < o) { sh1[threadIdx.x] += sh1[threadIdx.x+o]; sh2[threadIdx.x] += sh2[threadIdx.x+o]; }
        __syncthreads();
    }
    if (threadIdx.x == 0) {
        float m = sh1[0] * (1.f/16384.f);
        float var = sh2[0] * (1.f/16384.f) - m*m;
        g_mean[bc] = m;
        g_rsig[bc] = rsqrtf(var + 1e-5f);
    }
}

// ---------------- SPADE shared conv: mask(3) -> actv(128), relu ----------------
__global__ void sconv_kernel(const float* __restrict__ mask,
                             const float* __restrict__ w,
                             const float* __restrict__ bias) {
    int idx = blockIdx.x*256 + threadIdx.x;
    if (idx >= B_*NH_*HH*WW) return;
    int x = idx & 127, y = (idx >> 7) & 127, nh = (idx >> 14) & 127, b = idx >> 21;
    float acc = __ldg(&bias[nh]);
    const float* wp = w + nh*27;
    const float* mp = mask + (size_t)b*3*16384;
    #pragma unroll
    for (int i = 0; i < 3; ++i) {
        #pragma unroll
        for (int dy = 0; dy < 3; ++dy) {
            int gy = y + dy - 1;
            if ((unsigned)gy >= 128u) continue;
            #pragma unroll
            for (int dx = 0; dx < 3; ++dx) {
                int gx = x + dx - 1;
                if ((unsigned)gx >= 128u) continue;
                acc = fmaf(__ldg(&mp[i*16384 + (gy<<7) + gx]),
                           __ldg(&wp[i*9 + dy*3 + dx]), acc);
            }
        }
    }
    g_actv[idx] = fmaxf(acc, 0.f);
}

// ---------------- fused: spade gamma/beta convs + table gather + blend + denorm --------
// block = 8x16 pixel tile, 256 threads: 16 cout-groups (8 couts of 128) x 16 pixel-groups (8 px)
// smem (floats): sW[16*9*132]=19008 | sA2[16*200 u64]=6400 | sTg 2880 | sTb 2880 | sR 64
#define OFF_A  19008
#define OFF_TG 25408
#define OFF_TB 28288
#define OFF_R  31168
#define SMEM_FLOATS 31232
#define SMEM_BYTES (SMEM_FLOATS*4)

__global__ __launch_bounds__(256) void final_kernel(
    const float* __restrict__ x_in,
    const float* __restrict__ sgw, const float* __restrict__ sgb,
    const float* __restrict__ sbw, const float* __restrict__ sbb,
    const float* __restrict__ cgb, const float* __restrict__ cbb,
    const float* __restrict__ bgam, const float* __restrict__ bbet,
    float* __restrict__ out)
{
    extern __shared__ float sm[];
    float* sW  = sm;
    u64*   sA2 = (u64*)(sm + OFF_A);    // duplicated (a,a) pairs, [cin][10][20]
    float* sTg = sm + OFF_TG;
    float* sTb = sm + OFF_TB;
    unsigned char* sR = (unsigned char*)(sm + OFF_R);

    int t = threadIdx.x;
    int b = blockIdx.z;
    int ty0 = blockIdx.y * 8, tx0 = blockIdx.x * 16;
    int cg = t >> 4, pg = t & 15;
    int c0 = cg * 8;
    int py = pg >> 1, px0 = (pg & 1) * 8;

    // prologue: tables + region halo
    for (int idx = t; idx < 2880; idx += 256) {
        sTg[idx] = g_Tg[b*2880 + idx];
        sTb[idx] = g_Tb[b*2880 + idx];
    }
    for (int idx = t; idx < 200; idx += 256) {
        int yy = idx / 20, xx = idx - yy*20;
        int gy = ty0 + yy - 1, gx = tx0 + xx - 1;
        unsigned char r = 5;
        if (xx < 18 && (unsigned)gy < 128u && (unsigned)gx < 128u)
            r = g_rmap[(b << 14) + (gy << 7) + gx];
        sR[idx] = r;
    }

    // packed accumulators: acc2[i2][j] holds couts (c0+2*i2, c0+2*i2+1), pixel j
    u64 acc2[4][8];
    #pragma unroll
    for (int i = 0; i < 4; ++i)
        #pragma unroll
        for (int j = 0; j < 8; ++j) acc2[i][j] = 0ull;

    // main conv over 128 input channels, chunks of 16
    for (int cc = 0; cc < 8; ++cc) {
        int ci0 = cc * 16;
        __syncthreads();
        // stage weights: sW[(cin*9+tap)*132 + c128]
        for (int idx = t; idx < 18432; idx += 256) {
            int c128 = idx / 144; int rem = idx - c128*144;
            int cin = rem / 9;    int tap = rem - cin*9;
            const float* wsrc = (c128 < 64) ? sgw : sbw;
            sW[(cin*9 + tap)*132 + c128] =
                __ldg(&wsrc[(((c128 & 63)*128) + ci0 + cin)*9 + tap]);
        }
        // stage actv halo duplicated: sA2[cin*200 + yy*20 + xx] = (v, v)
        for (int idx = t; idx < 2880; idx += 256) {
            int cin = idx / 180; int rem = idx - cin*180;
            int yy = rem / 18;   int xx = rem - yy*18;
            int gy = ty0 + yy - 1, gx = tx0 + xx - 1;
            float v = 0.f;
            if ((unsigned)gy < 128u && (unsigned)gx < 128u)
                v = g_actv[(((size_t)(b*128 + ci0 + cin)) << 14) + (gy << 7) + gx];
            ((float2*)sA2)[cin*200 + yy*20 + xx] = make_float2(v, v);
        }
        __syncthreads();

        const u64* aBase = sA2 + py*20 + px0;
        #pragma unroll 1
        for (int cin = 0; cin < 16; ++cin) {
            const u64* aC = aBase + cin*200;
            const float* wC = sW + c0 + cin*9*132;
            #pragma unroll
            for (int dy = 0; dy < 3; ++dy) {
                u64 ar[10];
                #pragma unroll
                for (int q = 0; q < 10; ++q) ar[q] = aC[dy*20 + q];
                #pragma unroll
                for (int dx = 0; dx < 3; ++dx) {
                    const u64* wp = (const u64*)(wC + (dy*3 + dx)*132);
                    u64 wv[4];
                    #pragma unroll
                    for (int i = 0; i < 4; ++i) wv[i] = wp[i];
                    #pragma unroll
                    for (int i = 0; i < 4; ++i)
                        #pragma unroll
                        for (int j = 0; j < 8; ++j)
                            acc2[i][j] = ffma2(wv[i], ar[dx + j], acc2[i][j]);
                }
            }
        }
    }

    // unpack accumulators
    float acc[8][8];
    #pragma unroll
    for (int i = 0; i < 4; ++i)
        #pragma unroll
        for (int j = 0; j < 8; ++j) {
            unsigned lo = (unsigned)(acc2[i][j] & 0xffffffffull);
            unsigned hi = (unsigned)(acc2[i][j] >> 32);
            acc[2*i][j]   = __uint_as_float(lo);
            acc[2*i+1][j] = __uint_as_float(hi);
        }

    // epilogue: table gather + biases + sigmoid blend
    float ga = 1.f / (1.f + __expf(-__ldg(bgam)));
    float ba = 1.f / (1.f + __expf(-__ldg(bbet)));
    bool isG = (c0 < 64);
    int cB = c0 & 63;
    float blend = isG ? ga : ba;
    const float* sT    = isG ? sTg : sTb;
    const float* cbias = isG ? cgb : cbb;
    const float* spbias= isG ? sgb : sbb;

    #pragma unroll
    for (int i = 0; i < 8; ++i) {
        int c = cB + i;
        float cbv = __ldg(&cbias[c]);
        float sbv = __ldg(&spbias[c]);
        #pragma unroll
        for (int j = 0; j < 8; ++j) {
            float avg = cbv;
            #pragma unroll
            for (int tap = 0; tap < 9; ++tap) {
                int dy = tap / 3, dx = tap - dy*3;
                int rr = sR[(py + dy)*20 + px0 + j + dx];
                if (rr < 5) avg += sT[(tap*5 + rr)*64 + c];
            }
            float sp = acc[i][j] + sbv;
            acc[i][j] = blend*avg + (1.f - blend)*sp;
        }
    }

    __syncthreads();  // everyone done reading sW -> reuse as [128 ch][128 px] buffer
    #pragma unroll
    for (int i = 0; i < 8; ++i)
        #pragma unroll
        for (int j = 0; j < 8; ++j)
            sW[(c0 + i)*128 + py*16 + px0 + j] = acc[i][j];
    __syncthreads();

    // combine gamma/beta with instance-normed x
    for (int idx = t; idx < 8192; idx += 256) {
        int c = idx >> 7, pl = idx & 127;
        int y = ty0 + (pl >> 4), x = tx0 + (pl & 15);
        int ch = (b << 6) + c;
        float xv = x_in[((size_t)ch << 14) + (y << 7) + x];
        float xn = (xv - g_mean[ch]) * g_rsig[ch];
        float gf = sW[(c << 7) + pl];
        float bf = sW[((c + 64) << 7) + pl];
        out[((size_t)ch << 14) + (y << 7) + x] = fmaf(xn, gf, xn) + bf;
    }
}

// ---------------- launch ----------------
extern "C" void kernel_launch(void* const* d_in, const int* in_sizes, int n_in,
                              void* d_out, int out_size) {
    const float* x      = (const float*)d_in[0];
    const float* segmap = (const float*)d_in[1];
    const float* codes  = (const float*)d_in[2];
    const float* mask   = (const float*)d_in[3];
    const float* fc_w   = (const float*)d_in[4];
    const float* fc_b   = (const float*)d_in[5];
    const float* cgw    = (const float*)d_in[6];
    const float* cgb    = (const float*)d_in[7];
    const float* cbw    = (const float*)d_in[8];
    const float* cbb    = (const float*)d_in[9];
    const float* ssw    = (const float*)d_in[10];
    const float* ssb    = (const float*)d_in[11];
    const float* sgw    = (const float*)d_in[12];
    const float* sgb    = (const float*)d_in[13];
    const float* sbw    = (const float*)d_in[14];
    const float* sbb    = (const float*)d_in[15];
    const float* bgam   = (const float*)d_in[16];
    const float* bbet   = (const float*)d_in[17];
    float* out = (float*)d_out;

    cudaFuncSetAttribute(final_kernel, cudaFuncAttributeMaxDynamicSharedMemorySize, SMEM_BYTES);

    mu_kernel<<<B_*F_, 512>>>(codes, fc_w, fc_b);
    region_kernel<<<(B_*HH*WW + 255)/256, 256>>>(segmap);
    table_kernel<<<2880, 256>>>(cgw, cbw);
    stats_kernel<<<B_*C_, 256>>>(x);
    sconv_kernel<<<(B_*NH_*HH*WW + 255)/256, 256>>>(mask, ssw, ssb);

    dim3 grid(WW/16, HH/8, B_);
    final_kernel<<<grid, 256, SMEM_BYTES>>>(x, sgw, sgb, sbw, sbb,
                                            cgb, cbb, bgam, bbet, out);
}

// round 4
// speedup vs baseline: 1.4787x; 1.4787x over previous
#include <cuda_runtime.h>
#include <cuda_bf16.h>
#include <math.h>
#include <stdint.h>

#define B_  4
#define C_  64
#define HH  128
#define WW  128
#define F_  5
#define L_  512
#define NH_ 128

// ---------------- device scratch ----------------
__device__ float g_mu[B_*F_*L_];
__device__ unsigned char g_rmap[B_*HH*WW];
__device__ float g_Tg[B_*9*F_*C_];               // [b][tap][f][c]
__device__ float g_Tb[B_*9*F_*C_];
__device__ __nv_bfloat16 g_act_h[(size_t)B_*HH*WW*NH_];  // NHWC hi
__device__ __nv_bfloat16 g_act_l[(size_t)B_*HH*WW*NH_];  // NHWC lo
__device__ __nv_bfloat16 g_Aw_h[9*128*128];      // [tap][c128][nh] hi
__device__ __nv_bfloat16 g_Aw_l[9*128*128];      // lo
__device__ float g_mean[B_*C_];
__device__ float g_rsig[B_*C_];

// ---------------- helpers ----------------
__device__ __forceinline__ uint32_t smem_u32(const void* p) {
    uint32_t a;
    asm("{ .reg .u64 t; cvta.to.shared.u64 t, %1; cvt.u32.u64 %0, t; }" : "=r"(a) : "l"(p));
    return a;
}
__device__ __forceinline__ uint32_t lds32(uint32_t a) {
    uint32_t v;
    asm volatile("ld.shared.b32 %0, [%1];" : "=r"(v) : "r"(a));
    return v;
}
__device__ __forceinline__ void cpa16(uint32_t dst, const void* src, uint32_t ssz) {
    asm volatile("cp.async.ca.shared.global [%0], [%1], 16, %2;"
                 :: "r"(dst), "l"(src), "r"(ssz) : "memory");
}
__device__ __forceinline__ void mma_bf16(float* d, const uint32_t* a, const uint32_t* b) {
    asm volatile("mma.sync.aligned.m16n8k16.row.col.f32.bf16.bf16.f32 "
        "{%0,%1,%2,%3},{%4,%5,%6,%7},{%8,%9},{%0,%1,%2,%3};"
        : "+f"(d[0]), "+f"(d[1]), "+f"(d[2]), "+f"(d[3])
        : "r"(a[0]), "r"(a[1]), "r"(a[2]), "r"(a[3]), "r"(b[0]), "r"(b[1]));
}

// ---------------- mu = relu(codes @ fc_w^T + fc_b) ----------------
__global__ void mu_kernel(const float* __restrict__ codes,
                          const float* __restrict__ fc_w,
                          const float* __restrict__ fc_b) {
    __shared__ float sc[L_];
    int bf = blockIdx.x;
    int f = bf % F_;
    int k = threadIdx.x;
    sc[k] = codes[bf*L_ + k];
    __syncthreads();
    const float* wp = fc_w + ((size_t)f*L_ + k)*L_;
    float acc = fc_b[f*L_ + k];
    #pragma unroll 4
    for (int l = 0; l < L_; ++l) acc = fmaf(sc[l], wp[l], acc);
    g_mu[bf*L_ + k] = fmaxf(acc, 0.f);
}

// ---------------- region map ----------------
__global__ void region_kernel(const float* __restrict__ seg) {
    int p = blockIdx.x*256 + threadIdx.x;
    if (p >= B_*HH*WW) return;
    int b = p >> 14, pix = p & 16383;
    int r = 5;
    #pragma unroll
    for (int j = 0; j < F_; ++j)
        if (seg[(b*F_ + j)*16384 + pix] > 0.f) r = j;
    g_rmap[p] = (unsigned char)r;
}

// ---------------- tables T[b,tap,f,c] ----------------
__global__ void table_kernel(const float* __restrict__ cgw,
                             const float* __restrict__ cbw) {
    int gt = blockIdx.x*256 + threadIdx.x;
    int e = gt >> 5, lane = gt & 31;
    int tbl = e / 11520; int r = e - tbl*11520;
    int b = r / 2880;    int r2 = r - b*2880;
    int tap = r2 / 320;  int r3 = r2 - tap*320;
    int f = r3 >> 6;     int c = r3 & 63;
    int dy = tap / 3, dx = tap - dy*3;
    const float* w = tbl ? cbw : cgw;
    const float* m = g_mu + (b*F_ + f)*L_;
    float s = 0.f;
    for (int l = lane; l < L_; l += 32)
        s = fmaf(w[(((size_t)c*L_ + l)*3 + dy)*3 + dx], m[l], s);
    #pragma unroll
    for (int o = 16; o > 0; o >>= 1) s += __shfl_down_sync(0xffffffffu, s, o);
    if (lane == 0)
        (tbl ? g_Tb : g_Tg)[((b*9 + tap)*F_ + f)*64 + c] = s;
}

// ---------------- instance norm stats ----------------
__global__ void stats_kernel(const float* __restrict__ x) {
    int bc = blockIdx.x;
    const float* p = x + (size_t)bc*16384;
    float s = 0.f, s2 = 0.f;
    for (int i = threadIdx.x; i < 16384; i += 256) {
        float v = p[i]; s += v; s2 = fmaf(v, v, s2);
    }
    __shared__ float sh1[256], sh2[256];
    sh1[threadIdx.x] = s; sh2[threadIdx.x] = s2;
    __syncthreads();
    for (int o = 128; o > 0; o >>= 1) {
        if (threadIdx.x < o) { sh1[threadIdx.x] += sh1[threadIdx.x+o]; sh2[threadIdx.x] += sh2[threadIdx.x+o]; }
        __syncthreads();
    }
    if (threadIdx.x == 0) {
        float m = sh1[0] * (1.f/16384.f);
        float var = sh2[0] * (1.f/16384.f) - m*m;
        g_mean[bc] = m;
        g_rsig[bc] = rsqrtf(var + 1e-5f);
    }
}

// ---------------- weight prep: split to bf16 hi/lo, layout [tap][c128][nh] ----------------
__global__ void wprep_kernel(const float* __restrict__ sgw,
                             const float* __restrict__ sbw) {
    int idx = blockIdx.x*256 + threadIdx.x;
    if (idx >= 9*128*128) return;
    int nh = idx & 127, c = (idx >> 7) & 127, tap = idx >> 14;
    const float* src = (c < 64) ? sgw : sbw;
    float v = src[(((c & 63)*128) + nh)*9 + tap];
    __nv_bfloat16 h = __float2bfloat16_rn(v);
    float lo = v - __bfloat162float(h);
    g_Aw_h[idx] = h;
    g_Aw_l[idx] = __float2bfloat16_rn(lo);
}

// ---------------- SPADE shared conv -> NHWC bf16 hi/lo ----------------
__global__ void sconv_kernel(const float* __restrict__ mask,
                             const float* __restrict__ w,
                             const float* __restrict__ bias) {
    __shared__ float sw[NH_*27];
    __shared__ float smk[3][3][34];
    int t = threadIdx.x;
    int b = blockIdx.z, y = blockIdx.y, x0 = blockIdx.x*32;
    for (int i = t; i < NH_*27; i += 256) sw[i] = w[i];
    for (int i = t; i < 3*3*34; i += 256) {
        int ch = i / 102, rem = i - ch*102;
        int r = rem / 34, cx = rem - r*34;
        int gy = y + r - 1, gx = x0 + cx - 1;
        float v = 0.f;
        if ((unsigned)gy < 128u && (unsigned)gx < 128u)
            v = mask[((b*3 + ch) << 14) + (gy << 7) + gx];
        smk[ch][r][cx] = v;
    }
    __syncthreads();
    int px = t >> 3, g = t & 7;
    float mv[3][3][3];
    #pragma unroll
    for (int ch = 0; ch < 3; ++ch)
        #pragma unroll
        for (int r = 0; r < 3; ++r)
            #pragma unroll
            for (int d = 0; d < 3; ++d)
                mv[ch][r][d] = smk[ch][r][px + d];
    int nh0 = g*16;
    unsigned hw[8], lw[8];
    #pragma unroll 2
    for (int k = 0; k < 16; ++k) {
        int nh = nh0 + k;
        float acc = __ldg(&bias[nh]);
        const float* wp = &sw[nh*27];
        #pragma unroll
        for (int ch = 0; ch < 3; ++ch)
            #pragma unroll
            for (int r = 0; r < 3; ++r)
                #pragma unroll
                for (int d = 0; d < 3; ++d)
                    acc = fmaf(mv[ch][r][d], wp[ch*9 + r*3 + d], acc);
        acc = fmaxf(acc, 0.f);
        __nv_bfloat16 h = __float2bfloat16_rn(acc);
        __nv_bfloat16 l = __float2bfloat16_rn(acc - __bfloat162float(h));
        unsigned hb = (unsigned)__bfloat16_as_ushort(h);
        unsigned lb = (unsigned)__bfloat16_as_ushort(l);
        if (k & 1) { hw[k>>1] |= hb << 16; lw[k>>1] |= lb << 16; }
        else       { hw[k>>1]  = hb;       lw[k>>1]  = lb; }
    }
    size_t base = (((size_t)(b*128 + y))*128 + (x0 + px))*128 + nh0;
    uint4* dh = (uint4*)&g_act_h[base];
    uint4* dl = (uint4*)&g_act_l[base];
    dh[0] = make_uint4(hw[0], hw[1], hw[2], hw[3]);
    dh[1] = make_uint4(hw[4], hw[5], hw[6], hw[7]);
    dl[0] = make_uint4(lw[0], lw[1], lw[2], lw[3]);
    dl[1] = make_uint4(lw[4], lw[5], lw[6], lw[7]);
}

// ---------------- fused HMMA conv + table gather + blend + denorm ----------------
// block = 1 image row (128 px), 256 threads (8 warps: 4M x 2N), M=128 couts.
// K = 9 taps x 128 nh in 72 chunks of 16; cp.async double-buffered.
#define ST_A_H 0
#define ST_A_L 6144
#define ST_B_H 12288
#define ST_B_L 18432
#define STAGE_BYTES 24576
#define OFF_TG 67584
#define OFF_TB (67584 + 11520)
#define OFF_R  (67584 + 23040)
#define DYN_BYTES (67584 + 23040 + 512)

__global__ __launch_bounds__(256, 1) void final_kernel(
    const float* __restrict__ x_in,
    const float* __restrict__ sgb, const float* __restrict__ sbb,
    const float* __restrict__ cgb, const float* __restrict__ cbb,
    const float* __restrict__ bgam, const float* __restrict__ bbet,
    float* __restrict__ out)
{
    extern __shared__ char dsm[];
    uint32_t sb = smem_u32(dsm);
    float* sGB = (float*)dsm;                  // [128 c][132 px] (epilogue, overlaps staging)
    float* sTg = (float*)(dsm + OFF_TG);
    float* sTb = (float*)(dsm + OFF_TB);
    unsigned char* sR = (unsigned char*)(dsm + OFF_R);   // [3][132]

    int t = threadIdx.x, wid = t >> 5, lane = t & 31;
    int b = blockIdx.y, y = blockIdx.x;
    int wm = wid >> 1, wn = wid & 1, g = lane >> 2, tg = lane & 3;

    // prologue: tables + region halo
    for (int i = t; i < 2880; i += 256) {
        sTg[i] = g_Tg[b*2880 + i];
        sTb[i] = g_Tb[b*2880 + i];
    }
    for (int i = t; i < 3*132; i += 256) {
        int r = i / 132, cx = i - r*132;
        int gy = y - 1 + r, gx = cx - 1;
        unsigned char rr = 5;
        if (cx < 130 && (unsigned)gy < 128u && (unsigned)gx < 128u)
            rr = g_rmap[(b << 14) + (gy << 7) + gx];
        sR[i] = rr;
    }

    // staging (thread -> one 16B cp.async per buffer)
    int rowi = t >> 1, half = t & 1;
    auto stage = [&](int ck) {
        int s = ck & 1;
        int tap = ck >> 3, kc = ck & 7;
        uint32_t base = sb + s*STAGE_BYTES;
        uint32_t doff = rowi*48 + half*16;
        // A: weights [c128][16 nh]
        size_t aoff = (size_t)tap*16384 + rowi*128 + kc*16 + half*8;
        cpa16(base + ST_A_H + doff, g_Aw_h + aoff, 16);
        cpa16(base + ST_A_L + doff, g_Aw_l + aoff, 16);
        // B: activations [px][16 nh], zero-filled halo
        int dy = tap / 3, dx = tap - 3*dy;
        int gy = y + dy - 1, gx = rowi + dx - 1;
        bool in = ((unsigned)gy < 128u) && ((unsigned)gx < 128u);
        int cy = in ? gy : 0, cx = in ? gx : 0;
        size_t boff = (((size_t)(b*128 + cy))*128 + cx)*128 + kc*16 + half*8;
        uint32_t ssz = in ? 16u : 0u;
        cpa16(base + ST_B_H + doff, g_act_h + boff, ssz);
        cpa16(base + ST_B_L + doff, g_act_l + boff, ssz);
    };

    float acc[2][8][4];
    #pragma unroll
    for (int mt = 0; mt < 2; ++mt)
        #pragma unroll
        for (int nt = 0; nt < 8; ++nt)
            #pragma unroll
            for (int ci = 0; ci < 4; ++ci) acc[mt][nt][ci] = 0.f;

    stage(0);
    asm volatile("cp.async.commit_group;" ::: "memory");

    for (int ck = 0; ck < 72; ++ck) {
        if (ck < 71) {
            stage(ck + 1);
            asm volatile("cp.async.commit_group;" ::: "memory");
            asm volatile("cp.async.wait_group 1;" ::: "memory");
        } else {
            asm volatile("cp.async.wait_group 0;" ::: "memory");
        }
        __syncthreads();

        uint32_t base = sb + (ck & 1)*STAGE_BYTES;
        uint32_t aRow = base + (wm*32 + g)*48 + tg*4;
        uint32_t bRow = base + (wn*64 + g)*48 + tg*4;

        uint32_t ah[2][4], al[2][4], bb[8][2];
        #pragma unroll
        for (int mt = 0; mt < 2; ++mt) {
            uint32_t u = aRow + mt*768;
            ah[mt][0] = lds32(u + ST_A_H);       ah[mt][1] = lds32(u + ST_A_H + 384);
            ah[mt][2] = lds32(u + ST_A_H + 16);  ah[mt][3] = lds32(u + ST_A_H + 400);
            al[mt][0] = lds32(u + ST_A_L);       al[mt][1] = lds32(u + ST_A_L + 384);
            al[mt][2] = lds32(u + ST_A_L + 16);  al[mt][3] = lds32(u + ST_A_L + 400);
        }
        #pragma unroll
        for (int nt = 0; nt < 8; ++nt) {
            uint32_t u = bRow + ST_B_H + nt*384;
            bb[nt][0] = lds32(u); bb[nt][1] = lds32(u + 16);
        }
        #pragma unroll
        for (int nt = 0; nt < 8; ++nt)
            #pragma unroll
            for (int mt = 0; mt < 2; ++mt) {
                mma_bf16(acc[mt][nt], ah[mt], bb[nt]);
                mma_bf16(acc[mt][nt], al[mt], bb[nt]);
            }
        #pragma unroll
        for (int nt = 0; nt < 8; ++nt) {
            uint32_t u = bRow + ST_B_L + nt*384;
            bb[nt][0] = lds32(u); bb[nt][1] = lds32(u + 16);
        }
        #pragma unroll
        for (int nt = 0; nt < 8; ++nt)
            #pragma unroll
            for (int mt = 0; mt < 2; ++mt)
                mma_bf16(acc[mt][nt], ah[mt], bb[nt]);

        __syncthreads();
    }

    // ---- epilogue: gather + blend into sGB [c128][132] ----
    float ga = 1.f / (1.f + __expf(-__ldg(bgam)));
    float ba = 1.f / (1.f + __expf(-__ldg(bbet)));

    #pragma unroll
    for (int mt = 0; mt < 2; ++mt)
        #pragma unroll
        for (int hi = 0; hi < 2; ++hi) {
            int m = wm*32 + mt*16 + g + hi*8;
            bool isG = (m < 64);
            int cc = m & 63;
            float blend = isG ? ga : ba;
            const float* sT = isG ? sTg : sTb;
            float cbv = __ldg(isG ? &cgb[cc] : &cbb[cc]);
            float sbv = __ldg(isG ? &sgb[cc] : &sbb[cc]);
            #pragma unroll
            for (int nt = 0; nt < 8; ++nt)
                #pragma unroll
                for (int lo = 0; lo < 2; ++lo) {
                    int px = wn*64 + nt*8 + tg*2 + lo;
                    float val = acc[mt][nt][hi*2 + lo];
                    float avg = cbv;
                    #pragma unroll
                    for (int tp = 0; tp < 9; ++tp) {
                        int ddy = tp / 3, ddx = tp - 3*ddy;
                        int rr = sR[ddy*132 + px + ddx];
                        if (rr < 5) avg += sT[(tp*5 + rr)*64 + cc];
                    }
                    sGB[m*132 + px] = blend*avg + (1.f - blend)*(val + sbv);
                }
        }
    __syncthreads();

    // ---- combine with instance-normed x (coalesced) ----
    for (int idx = t; idx < 8192; idx += 256) {
        int c = idx >> 7, px = idx & 127;
        int ch = (b << 6) + c;
        float xv = x_in[((size_t)ch << 14) + (y << 7) + px];
        float xn = (xv - __ldg(&g_mean[ch])) * __ldg(&g_rsig[ch]);
        float gf = sGB[c*132 + px];
        float bf = sGB[(c + 64)*132 + px];
        out[((size_t)ch << 14) + (y << 7) + px] = fmaf(xn, gf, xn) + bf;
    }
}

// ---------------- launch ----------------
extern "C" void kernel_launch(void* const* d_in, const int* in_sizes, int n_in,
                              void* d_out, int out_size) {
    const float* x      = (const float*)d_in[0];
    const float* segmap = (const float*)d_in[1];
    const float* codes  = (const float*)d_in[2];
    const float* mask   = (const float*)d_in[3];
    const float* fc_w   = (const float*)d_in[4];
    const float* fc_b   = (const float*)d_in[5];
    const float* cgw    = (const float*)d_in[6];
    const float* cgb    = (const float*)d_in[7];
    const float* cbw    = (const float*)d_in[8];
    const float* cbb    = (const float*)d_in[9];
    const float* ssw    = (const float*)d_in[10];
    const float* ssb    = (const float*)d_in[11];
    const float* sgw    = (const float*)d_in[12];
    const float* sgb    = (const float*)d_in[13];
    const float* sbw    = (const float*)d_in[14];
    const float* sbb    = (const float*)d_in[15];
    const float* bgam   = (const float*)d_in[16];
    const float* bbet   = (const float*)d_in[17];
    float* out = (float*)d_out;

    cudaFuncSetAttribute(final_kernel, cudaFuncAttributeMaxDynamicSharedMemorySize, DYN_BYTES);

    mu_kernel<<<B_*F_, 512>>>(codes, fc_w, fc_b);
    region_kernel<<<(B_*HH*WW + 255)/256, 256>>>(segmap);
    table_kernel<<<2880, 256>>>(cgw, cbw);
    stats_kernel<<<B_*C_, 256>>>(x);
    wprep_kernel<<<(9*128*128 + 255)/256, 256>>>(sgw, sbw);
    {
        dim3 g(4, 128, 4);
        sconv_kernel<<<g, 256>>>(mask, ssw, ssb);
    }
    {
        dim3 g(128, 4);
        final_kernel<<<g, 256, DYN_BYTES>>>(x, sgb, sbb, cgb, cbb, bgam, bbet, out);
    }
}

// round 5
// speedup vs baseline: 1.6022x; 1.0836x over previous
#include <cuda_runtime.h>
#include <cuda_bf16.h>
#include <math.h>
#include <stdint.h>

#define B_  4
#define C_  64
#define HH  128
#define WW  128
#define F_  5
#define L_  512
#define NH_ 128

// ---------------- device scratch ----------------
__device__ float g_mu[B_*F_*L_];
__device__ unsigned char g_rmap[B_*HH*WW];
__device__ float g_Tg[B_*9*F_*C_];               // [b][tap][f][c]
__device__ float g_Tb[B_*9*F_*C_];
__device__ __nv_bfloat16 g_act_h[(size_t)B_*HH*WW*NH_];  // NHWC hi
__device__ __nv_bfloat16 g_act_l[(size_t)B_*HH*WW*NH_];  // NHWC lo
__device__ __nv_bfloat16 g_Aw_h[9*128*128];      // [tap][c128][nh] hi
__device__ __nv_bfloat16 g_Aw_l[9*128*128];      // lo
__device__ float g_mean[B_*C_];
__device__ float g_rsig[B_*C_];

// ---------------- helpers ----------------
__device__ __forceinline__ uint32_t smem_u32(const void* p) {
    uint32_t a;
    asm("{ .reg .u64 t; cvta.to.shared.u64 t, %1; cvt.u32.u64 %0, t; }" : "=r"(a) : "l"(p));
    return a;
}
__device__ __forceinline__ void cpa16(uint32_t dst, const void* src, uint32_t ssz) {
    asm volatile("cp.async.ca.shared.global [%0], [%1], 16, %2;"
                 :: "r"(dst), "l"(src), "r"(ssz) : "memory");
}
__device__ __forceinline__ void ldsm4(uint32_t* r, uint32_t addr) {
    asm volatile("ldmatrix.sync.aligned.m8n8.x4.shared.b16 {%0,%1,%2,%3}, [%4];"
        : "=r"(r[0]), "=r"(r[1]), "=r"(r[2]), "=r"(r[3]) : "r"(addr));
}
__device__ __forceinline__ void mma_bf16(float* d, const uint32_t* a, const uint32_t* b) {
    asm volatile("mma.sync.aligned.m16n8k16.row.col.f32.bf16.bf16.f32 "
        "{%0,%1,%2,%3},{%4,%5,%6,%7},{%8,%9},{%0,%1,%2,%3};"
        : "+f"(d[0]), "+f"(d[1]), "+f"(d[2]), "+f"(d[3])
        : "r"(a[0]), "r"(a[1]), "r"(a[2]), "r"(a[3]), "r"(b[0]), "r"(b[1]));
}

// ---------------- mu = relu(codes @ fc_w^T + fc_b) ----------------
__global__ void mu_kernel(const float* __restrict__ codes,
                          const float* __restrict__ fc_w,
                          const float* __restrict__ fc_b) {
    __shared__ float sc[L_];
    int bf = blockIdx.x;
    int f = bf % F_;
    int k = threadIdx.x;
    sc[k] = codes[bf*L_ + k];
    __syncthreads();
    const float* wp = fc_w + ((size_t)f*L_ + k)*L_;
    float acc = fc_b[f*L_ + k];
    #pragma unroll 4
    for (int l = 0; l < L_; ++l) acc = fmaf(sc[l], wp[l], acc);
    g_mu[bf*L_ + k] = fmaxf(acc, 0.f);
}

// ---------------- region map ----------------
__global__ void region_kernel(const float* __restrict__ seg) {
    int p = blockIdx.x*256 + threadIdx.x;
    if (p >= B_*HH*WW) return;
    int b = p >> 14, pix = p & 16383;
    int r = 5;
    #pragma unroll
    for (int j = 0; j < F_; ++j)
        if (seg[(b*F_ + j)*16384 + pix] > 0.f) r = j;
    g_rmap[p] = (unsigned char)r;
}

// ---------------- tables T[b,tap,f,c] ----------------
__global__ void table_kernel(const float* __restrict__ cgw,
                             const float* __restrict__ cbw) {
    int gt = blockIdx.x*256 + threadIdx.x;
    int e = gt >> 5, lane = gt & 31;
    int tbl = e / 11520; int r = e - tbl*11520;
    int b = r / 2880;    int r2 = r - b*2880;
    int tap = r2 / 320;  int r3 = r2 - tap*320;
    int f = r3 >> 6;     int c = r3 & 63;
    int dy = tap / 3, dx = tap - dy*3;
    const float* w = tbl ? cbw : cgw;
    const float* m = g_mu + (b*F_ + f)*L_;
    float s = 0.f;
    for (int l = lane; l < L_; l += 32)
        s = fmaf(w[(((size_t)c*L_ + l)*3 + dy)*3 + dx], m[l], s);
    #pragma unroll
    for (int o = 16; o > 0; o >>= 1) s += __shfl_down_sync(0xffffffffu, s, o);
    if (lane == 0)
        (tbl ? g_Tb : g_Tg)[((b*9 + tap)*F_ + f)*64 + c] = s;
}

// ---------------- instance norm stats ----------------
__global__ void stats_kernel(const float* __restrict__ x) {
    int bc = blockIdx.x;
    const float* p = x + (size_t)bc*16384;
    float s = 0.f, s2 = 0.f;
    for (int i = threadIdx.x; i < 16384; i += 256) {
        float v = p[i]; s += v; s2 = fmaf(v, v, s2);
    }
    __shared__ float sh1[256], sh2[256];
    sh1[threadIdx.x] = s; sh2[threadIdx.x] = s2;
    __syncthreads();
    for (int o = 128; o > 0; o >>= 1) {
        if (threadIdx.x < o) { sh1[threadIdx.x] += sh1[threadIdx.x+o]; sh2[threadIdx.x] += sh2[threadIdx.x+o]; }
        __syncthreads();
    }
    if (threadIdx.x == 0) {
        float m = sh1[0] * (1.f/16384.f);
        float var = sh2[0] * (1.f/16384.f) - m*m;
        g_mean[bc] = m;
        g_rsig[bc] = rsqrtf(var + 1e-5f);
    }
}

// ---------------- weight prep: split to bf16 hi/lo, layout [tap][c128][nh] ----------------
__global__ void wprep_kernel(const float* __restrict__ sgw,
                             const float* __restrict__ sbw) {
    int idx = blockIdx.x*256 + threadIdx.x;
    if (idx >= 9*128*128) return;
    int nh = idx & 127, c = (idx >> 7) & 127, tap = idx >> 14;
    const float* src = (c < 64) ? sgw : sbw;
    float v = src[(((c & 63)*128) + nh)*9 + tap];
    __nv_bfloat16 h = __float2bfloat16_rn(v);
    float lo = v - __bfloat162float(h);
    g_Aw_h[idx] = h;
    g_Aw_l[idx] = __float2bfloat16_rn(lo);
}

// ---------------- SPADE shared conv -> NHWC bf16 hi/lo ----------------
__global__ void sconv_kernel(const float* __restrict__ mask,
                             const float* __restrict__ w,
                             const float* __restrict__ bias) {
    __shared__ float sw[NH_*27];
    __shared__ float smk[3][3][34];
    int t = threadIdx.x;
    int b = blockIdx.z, y = blockIdx.y, x0 = blockIdx.x*32;
    for (int i = t; i < NH_*27; i += 256) sw[i] = w[i];
    for (int i = t; i < 3*3*34; i += 256) {
        int ch = i / 102, rem = i - ch*102;
        int r = rem / 34, cx = rem - r*34;
        int gy = y + r - 1, gx = x0 + cx - 1;
        float v = 0.f;
        if ((unsigned)gy < 128u && (unsigned)gx < 128u)
            v = mask[((b*3 + ch) << 14) + (gy << 7) + gx];
        smk[ch][r][cx] = v;
    }
    __syncthreads();
    int px = t >> 3, g = t & 7;
    float mv[3][3][3];
    #pragma unroll
    for (int ch = 0; ch < 3; ++ch)
        #pragma unroll
        for (int r = 0; r < 3; ++r)
            #pragma unroll
            for (int d = 0; d < 3; ++d)
                mv[ch][r][d] = smk[ch][r][px + d];
    int nh0 = g*16;
    unsigned hw[8], lw[8];
    #pragma unroll 2
    for (int k = 0; k < 16; ++k) {
        int nh = nh0 + k;
        float acc = __ldg(&bias[nh]);
        const float* wp = &sw[nh*27];
        #pragma unroll
        for (int ch = 0; ch < 3; ++ch)
            #pragma unroll
            for (int r = 0; r < 3; ++r)
                #pragma unroll
                for (int d = 0; d < 3; ++d)
                    acc = fmaf(mv[ch][r][d], wp[ch*9 + r*3 + d], acc);
        acc = fmaxf(acc, 0.f);
        __nv_bfloat16 h = __float2bfloat16_rn(acc);
        __nv_bfloat16 l = __float2bfloat16_rn(acc - __bfloat162float(h));
        unsigned hb = (unsigned)__bfloat16_as_ushort(h);
        unsigned lb = (unsigned)__bfloat16_as_ushort(l);
        if (k & 1) { hw[k>>1] |= hb << 16; lw[k>>1] |= lb << 16; }
        else       { hw[k>>1]  = hb;       lw[k>>1]  = lb; }
    }
    size_t base = (((size_t)(b*128 + y))*128 + (x0 + px))*128 + nh0;
    uint4* dh = (uint4*)&g_act_h[base];
    uint4* dl = (uint4*)&g_act_l[base];
    dh[0] = make_uint4(hw[0], hw[1], hw[2], hw[3]);
    dh[1] = make_uint4(hw[4], hw[5], hw[6], hw[7]);
    dl[0] = make_uint4(lw[0], lw[1], lw[2], lw[3]);
    dl[1] = make_uint4(lw[4], lw[5], lw[6], lw[7]);
}

// ---------------- fused HMMA conv + table gather + blend + denorm ----------------
// block = 1 image row (128 px), 256 threads (8 warps: 4M x 2N), M=128 couts.
// K = 9 taps x 128 nh, chunks of 32 (36 iters), 3-stage cp.async ring, ldmatrix.
// Stage layout: rows of 80B (64B data + 16B pad, conflict-free for LDSM).
#define ROWB   80
#define A_H    0
#define A_L    10240
#define B_H    20480
#define B_L    30720
#define STG    40960
#define OFF_TG (3*STG)
#define OFF_TB (OFF_TG + 11520)
#define OFF_R  (OFF_TB + 11520)
#define DYN_BYTES (OFF_R + 512)

__global__ __launch_bounds__(256, 1) void final_kernel(
    const float* __restrict__ x_in,
    const float* __restrict__ sgb, const float* __restrict__ sbb,
    const float* __restrict__ cgb, const float* __restrict__ cbb,
    const float* __restrict__ bgam, const float* __restrict__ bbet,
    float* __restrict__ out)
{
    extern __shared__ char dsm[];
    uint32_t sb = smem_u32(dsm);
    float* sGB = (float*)dsm;                  // [128 c][132 px] epilogue (aliases stages)
    float* sTg = (float*)(dsm + OFF_TG);
    float* sTb = (float*)(dsm + OFF_TB);
    unsigned char* sR = (unsigned char*)(dsm + OFF_R);   // [3][132]

    int t = threadIdx.x, wid = t >> 5, lane = t & 31;
    int b = blockIdx.y, y = blockIdx.x;
    int wm = wid >> 1, wn = wid & 1, g = lane >> 2, tg = lane & 3;

    // prologue: tables + region halo
    for (int i = t; i < 2880; i += 256) {
        sTg[i] = g_Tg[b*2880 + i];
        sTb[i] = g_Tb[b*2880 + i];
    }
    for (int i = t; i < 3*132; i += 256) {
        int r = i / 132, cx = i - r*132;
        int gy = y - 1 + r, gx = cx - 1;
        unsigned char rr = 5;
        if (cx < 130 && (unsigned)gy < 128u && (unsigned)gx < 128u)
            rr = g_rmap[(b << 14) + (gy << 7) + gx];
        sR[i] = rr;
    }

    // ldmatrix lane address bases
    int rowA = wm*32 + (lane & 7) + ((lane >> 3) & 1)*8;
    int kbA  = (lane >> 4)*16;
    uint32_t aBase = sb + rowA*ROWB + kbA;
    int nB  = wn*64 + (lane & 7) + ((lane >> 4) & 1)*8;
    int kbB = ((lane >> 3) & 1)*16;
    uint32_t bBase = sb + nB*ROWB + kbB;

    // staging: chunk ck = (tap = ck>>2, kc = ck&3), K=32 nh values
    int srow = t >> 1, sseg2 = (t & 1)*2;   // 2 segs per thread per sub-buffer
    auto stage = [&](int ck) {
        int s = ck; if (s >= 3) s %= 3;
        int tap = ck >> 2, kc = ck & 3;
        int dyy = tap / 3, dxx = tap - 3*dyy;
        uint32_t base = sb + s*STG;
        int gy = y + dyy - 1, gx = srow + dxx - 1;
        bool in = ((unsigned)gy < 128u) && ((unsigned)gx < 128u);
        size_t bbase = (((size_t)(b*128 + (in ? gy : 0)))*128 + (in ? gx : 0))*128 + kc*32;
        uint32_t ssz = in ? 16u : 0u;
        size_t abase = (size_t)tap*16384 + srow*128 + kc*32;
        #pragma unroll
        for (int q = 0; q < 2; ++q) {
            int seg = sseg2 + q;
            uint32_t doff = srow*ROWB + seg*16;
            cpa16(base + A_H + doff, g_Aw_h + abase + seg*8, 16);
            cpa16(base + A_L + doff, g_Aw_l + abase + seg*8, 16);
            cpa16(base + B_H + doff, g_act_h + bbase + seg*8, ssz);
            cpa16(base + B_L + doff, g_act_l + bbase + seg*8, ssz);
        }
    };

    float acc[2][8][4];
    #pragma unroll
    for (int mt = 0; mt < 2; ++mt)
        #pragma unroll
        for (int nt = 0; nt < 8; ++nt)
            #pragma unroll
            for (int ci = 0; ci < 4; ++ci) acc[mt][nt][ci] = 0.f;

    stage(0);
    asm volatile("cp.async.commit_group;" ::: "memory");
    stage(1);
    asm volatile("cp.async.commit_group;" ::: "memory");

    for (int ck = 0; ck < 36; ++ck) {
        if (ck < 35) asm volatile("cp.async.wait_group 1;" ::: "memory");
        else         asm volatile("cp.async.wait_group 0;" ::: "memory");
        __syncthreads();
        if (ck < 34) {
            stage(ck + 2);
            asm volatile("cp.async.commit_group;" ::: "memory");
        }

        uint32_t so = (uint32_t)((ck % 3))*STG;
        #pragma unroll
        for (int kh = 0; kh < 2; ++kh) {
            uint32_t ah[2][4], al[2][4], bh[4][4], bl[4][4];
            ldsm4(ah[0], aBase + so + A_H + kh*32);
            ldsm4(ah[1], aBase + so + A_H + kh*32 + 16*ROWB);
            ldsm4(al[0], aBase + so + A_L + kh*32);
            ldsm4(al[1], aBase + so + A_L + kh*32 + 16*ROWB);
            #pragma unroll
            for (int q = 0; q < 4; ++q)
                ldsm4(bh[q], bBase + so + B_H + kh*32 + q*16*ROWB);
            #pragma unroll
            for (int q = 0; q < 4; ++q)
                ldsm4(bl[q], bBase + so + B_L + kh*32 + q*16*ROWB);
            #pragma unroll
            for (int q = 0; q < 4; ++q)
                #pragma unroll
                for (int hf = 0; hf < 2; ++hf) {
                    int nt = 2*q + hf;
                    const uint32_t* bph = &bh[q][hf*2];
                    const uint32_t* bpl = &bl[q][hf*2];
                    #pragma unroll
                    for (int mt = 0; mt < 2; ++mt) {
                        mma_bf16(acc[mt][nt], ah[mt], bph);
                        mma_bf16(acc[mt][nt], al[mt], bph);
                        mma_bf16(acc[mt][nt], ah[mt], bpl);
                    }
                }
        }
    }
    __syncthreads();   // all reads of stage buffers done before sGB overwrites them

    // ---- epilogue: gather + blend into sGB [c128][132] ----
    float ga = 1.f / (1.f + __expf(-__ldg(bgam)));
    float ba = 1.f / (1.f + __expf(-__ldg(bbet)));

    #pragma unroll
    for (int mt = 0; mt < 2; ++mt)
        #pragma unroll
        for (int hi = 0; hi < 2; ++hi) {
            int m = wm*32 + mt*16 + g + hi*8;
            bool isG = (m < 64);
            int cc = m & 63;
            float blend = isG ? ga : ba;
            const float* sT = isG ? sTg : sTb;
            float cbv = __ldg(isG ? &cgb[cc] : &cbb[cc]);
            float sbv = __ldg(isG ? &sgb[cc] : &sbb[cc]);
            #pragma unroll
            for (int nt = 0; nt < 8; ++nt)
                #pragma unroll
                for (int lo = 0; lo < 2; ++lo) {
                    int px = wn*64 + nt*8 + tg*2 + lo;
                    float val = acc[mt][nt][hi*2 + lo];
                    float avg = cbv;
                    #pragma unroll
                    for (int tp = 0; tp < 9; ++tp) {
                        int ddy = tp / 3, ddx = tp - 3*ddy;
                        int rr = sR[ddy*132 + px + ddx];
                        if (rr < 5) avg += sT[(tp*5 + rr)*64 + cc];
                    }
                    sGB[m*132 + px] = blend*avg + (1.f - blend)*(val + sbv);
                }
        }
    __syncthreads();

    // ---- combine with instance-normed x (coalesced) ----
    for (int idx = t; idx < 8192; idx += 256) {
        int c = idx >> 7, px = idx & 127;
        int ch = (b << 6) + c;
        float xv = x_in[((size_t)ch << 14) + (y << 7) + px];
        float xn = (xv - __ldg(&g_mean[ch])) * __ldg(&g_rsig[ch]);
        float gf = sGB[c*132 + px];
        float bf = sGB[(c + 64)*132 + px];
        out[((size_t)ch << 14) + (y << 7) + px] = fmaf(xn, gf, xn) + bf;
    }
}

// ---------------- launch ----------------
extern "C" void kernel_launch(void* const* d_in, const int* in_sizes, int n_in,
                              void* d_out, int out_size) {
    const float* x      = (const float*)d_in[0];
    const float* segmap = (const float*)d_in[1];
    const float* codes  = (const float*)d_in[2];
    const float* mask   = (const float*)d_in[3];
    const float* fc_w   = (const float*)d_in[4];
    const float* fc_b   = (const float*)d_in[5];
    const float* cgw    = (const float*)d_in[6];
    const float* cgb    = (const float*)d_in[7];
    const float* cbw    = (const float*)d_in[8];
    const float* cbb    = (const float*)d_in[9];
    const float* ssw    = (const float*)d_in[10];
    const float* ssb    = (const float*)d_in[11];
    const float* sgw    = (const float*)d_in[12];
    const float* sgb    = (const float*)d_in[13];
    const float* sbw    = (const float*)d_in[14];
    const float* sbb    = (const float*)d_in[15];
    const float* bgam   = (const float*)d_in[16];
    const float* bbet   = (const float*)d_in[17];
    float* out = (float*)d_out;

    cudaFuncSetAttribute(final_kernel, cudaFuncAttributeMaxDynamicSharedMemorySize, DYN_BYTES);

    mu_kernel<<<B_*F_, 512>>>(codes, fc_w, fc_b);
    region_kernel<<<(B_*HH*WW + 255)/256, 256>>>(segmap);
    table_kernel<<<2880, 256>>>(cgw, cbw);
    stats_kernel<<<B_*C_, 256>>>(x);
    wprep_kernel<<<(9*128*128 + 255)/256, 256>>>(sgw, sbw);
    {
        dim3 g(4, 128, 4);
        sconv_kernel<<<g, 256>>>(mask, ssw, ssb);
    }
    {
        dim3 g(128, 4);
        final_kernel<<<g, 256, DYN_BYTES>>>(x, sgb, sbb, cgb, cbb, bgam, bbet, out);
    }
}